// round 15
// baseline (speedup 1.0000x reference)
#include <cuda_runtime.h>
#include <math.h>

#define V 50257
#define H 1024
#define E 1024
#define L 512
#define HE 2048
#define G3 3072
#define NP 16            // L-partitions for attn-apply (32 rows each)
#define NPF 128          // prefetch-role blocks appended to each small kernel

// prefetch segments over out_w, in float4 units (64 MB total = 4096K float4)
#define SEG0_OFF 0u
#define SEG0_LEN  524288u   // attn:  8 MB
#define SEG1_OFF  524288u
#define SEG1_LEN  524288u   // apply: 8 MB
#define SEG2_OFF 1048576u
#define SEG2_LEN 1048576u   // comb: 16 MB
#define SEG3_OFF 2097152u
#define SEG3_LEN 1835008u   // gru:  28 MB
#define SEG4_OFF 3932160u
#define SEG4_LEN  262144u   // hnew:  4 MB

// ---------------- scratch (no allocations allowed) ----------------
__device__ float g_attn_logits[L];
__device__ float g_att_part[NP * H];
__device__ float g_x[E];
__device__ float g_gi[G3];
__device__ float g_gh[G3];
__device__ float g_h[H];
__device__ float g_logits[V];
__device__ float g_pmax[64];
__device__ float g_psum[64];
__device__ float g_sink;     // prefetch discard (guard is never true)

__device__ __forceinline__ float warp_sum(float v) {
    #pragma unroll
    for (int o = 16; o; o >>= 1) v += __shfl_down_sync(0xffffffffu, v, o);
    return v;
}
__device__ __forceinline__ float warp_max(float v) {
    #pragma unroll
    for (int o = 16; o; o >>= 1) v = fmaxf(v, __shfl_down_sync(0xffffffffu, v, o));
    return v;
}
__device__ __forceinline__ float blk_sum(float v, float* s) {
    int lane = threadIdx.x & 31, w = threadIdx.x >> 5;
    v = warp_sum(v);
    if (lane == 0) s[w] = v;
    __syncthreads();
    int nw = (blockDim.x + 31) >> 5;
    v = (threadIdx.x < nw) ? s[threadIdx.x] : 0.0f;
    if (w == 0) v = warp_sum(v);
    __syncthreads();
    return v;
}
__device__ __forceinline__ float blk_max(float v, float* s) {
    int lane = threadIdx.x & 31, w = threadIdx.x >> 5;
    v = warp_max(v);
    if (lane == 0) s[w] = v;
    __syncthreads();
    int nw = (blockDim.x + 31) >> 5;
    v = (threadIdx.x < nw) ? s[threadIdx.x] : -INFINITY;
    if (w == 0) v = warp_max(v);
    __syncthreads();
    return v;
}
__device__ __forceinline__ float sigmoidf_(float x) { return 1.0f / (1.0f + expf(-x)); }

#define DOT4(a, b) ((a).x * (b).x + (a).y * (b).y + (a).z * (b).z + (a).w * (b).w)

// Stream one segment of out_w through L2 (discarded). 16 float4 in flight/thread.
__device__ __forceinline__ void pf_stream(const float4* seg, unsigned len_f4, int pbid) {
    const int tid = threadIdx.x;
    float4 acc = make_float4(0.f, 0.f, 0.f, 0.f);
    for (unsigned b = (unsigned)pbid * 4096u; b < len_f4; b += NPF * 4096u) {
        #pragma unroll
        for (int k = 0; k < 16; k++) {
            float4 t = seg[b + (unsigned)(k * 256 + tid)];
            acc.x += t.x; acc.y += t.y; acc.z += t.z; acc.w += t.w;
        }
    }
    if (acc.x == 1.0e38f && acc.y == -1.0e38f && acc.z == 1.0e37f) g_sink = acc.w;
}

// ---------------- 1) attention logits: warp-per-row + prefetch role ----------------
// grid = 64 + NPF
__global__ void k_attn(const int* __restrict__ tok, const float* __restrict__ hidden,
                       const float* __restrict__ embedding,
                       const float* __restrict__ attn_w, const float* __restrict__ attn_b,
                       const float* __restrict__ out_w) {
    __shared__ float4 sx[HE / 4];
    const int tid = threadIdx.x;
    if (blockIdx.x >= 64) {
        pf_stream((const float4*)out_w + SEG0_OFF, SEG0_LEN, blockIdx.x - 64);
        return;
    }
    {
        const float* emb = embedding + (size_t)tok[0] * E;
        sx[tid]       = *(const float4*)(emb + tid * 4);
        sx[tid + 256] = *(const float4*)(hidden + tid * 4);
    }
    __syncthreads();
    const int warp = tid >> 5, lane = tid & 31;
    const int row = blockIdx.x * 8 + warp;
    const float4* wr = (const float4*)(attn_w + (size_t)row * HE);
    float acc = 0.0f;
    float4 w[8];
    #pragma unroll
    for (int k = 0; k < 8; k++) w[k] = wr[lane + 32 * k];
    #pragma unroll
    for (int k = 0; k < 8; k++) { float4 x4 = sx[lane + 32 * k]; acc += DOT4(w[k], x4); }
    #pragma unroll
    for (int k = 0; k < 8; k++) w[k] = wr[256 + lane + 32 * k];
    #pragma unroll
    for (int k = 0; k < 8; k++) { float4 x4 = sx[256 + lane + 32 * k]; acc += DOT4(w[k], x4); }
    acc = warp_sum(acc);
    if (lane == 0) g_attn_logits[row] = acc + attn_b[row];
}

// ---------------- 2) attn partials + fused softmax + prefetch role ----------------
// grid = 64 + NPF (flattened: xb = bid & 3, y = bid >> 2)
__global__ void k_attnapply(const float* __restrict__ enc, float* __restrict__ out_aw,
                            const float* __restrict__ out_w) {
    __shared__ float s[32];
    __shared__ float sl[L];
    __shared__ float aw[32];
    __shared__ float bm, bs;
    const int tid = threadIdx.x;
    if (blockIdx.x >= 64) {
        pf_stream((const float4*)out_w + SEG1_OFF, SEG1_LEN, blockIdx.x - 64);
        return;
    }
    sl[tid]       = g_attn_logits[tid];
    sl[tid + 256] = g_attn_logits[tid + 256];
    __syncthreads();
    float m = fmaxf(sl[tid], sl[tid + 256]);
    m = blk_max(m, s);
    if (tid == 0) bm = m;
    __syncthreads();
    float e = expf(sl[tid] - bm) + expf(sl[tid + 256] - bm);
    float sum = blk_sum(e, s);
    if (tid == 0) bs = sum;
    __syncthreads();
    const int xb = blockIdx.x & 3, y = blockIdx.x >> 2;
    const int r0 = y * 32;
    if (tid < 32) {
        float wv = expf(sl[r0 + tid] - bm) / bs;
        aw[tid] = wv;
        if (xb == 0) out_aw[r0 + tid] = wv;
    }
    __syncthreads();
    const int col = xb * 256 + tid;
    float acc = 0.0f;
    #pragma unroll 8
    for (int l = 0; l < 32; l++) acc += aw[l] * enc[(size_t)(r0 + l) * H + col];
    g_att_part[y * H + col] = acc;
}

// ---------------- 3) x = relu([emb, att] @ comb_w.T + b) + prefetch role ----------------
// grid = 128 + NPF
__global__ void k_comb(const int* __restrict__ tok, const float* __restrict__ embedding,
                       const float* __restrict__ comb_w, const float* __restrict__ comb_b,
                       const float* __restrict__ out_w) {
    __shared__ float4 sx[HE / 4];
    const int tid = threadIdx.x;
    if (blockIdx.x >= 128) {
        pf_stream((const float4*)out_w + SEG2_OFF, SEG2_LEN, blockIdx.x - 128);
        return;
    }
    {
        const float* emb = embedding + (size_t)tok[0] * E;
        sx[tid] = *(const float4*)(emb + tid * 4);
        float4 a = make_float4(0.f, 0.f, 0.f, 0.f);
        #pragma unroll
        for (int p = 0; p < NP; p++) {
            float4 t = *(const float4*)(&g_att_part[p * H + tid * 4]);
            a.x += t.x; a.y += t.y; a.z += t.z; a.w += t.w;
        }
        sx[tid + 256] = a;
    }
    __syncthreads();
    const int warp = tid >> 5, lane = tid & 31;
    const int row = blockIdx.x * 8 + warp;
    const float4* wr = (const float4*)(comb_w + (size_t)row * HE);
    float acc = 0.0f;
    float4 w[8];
    #pragma unroll
    for (int k = 0; k < 8; k++) w[k] = wr[lane + 32 * k];
    #pragma unroll
    for (int k = 0; k < 8; k++) { float4 x4 = sx[lane + 32 * k]; acc += DOT4(w[k], x4); }
    #pragma unroll
    for (int k = 0; k < 8; k++) w[k] = wr[256 + lane + 32 * k];
    #pragma unroll
    for (int k = 0; k < 8; k++) { float4 x4 = sx[256 + lane + 32 * k]; acc += DOT4(w[k], x4); }
    acc = warp_sum(acc);
    if (lane == 0) g_x[row] = fmaxf(acc + comb_b[row], 0.0f);
}

// ---------------- 4) GRU matvecs: warp-per-row, 16 loads in flight + prefetch role ------
// grid = 384 + NPF
__global__ void k_gru(const float* __restrict__ w_ih, const float* __restrict__ w_hh,
                      const float* __restrict__ b_ih, const float* __restrict__ b_hh,
                      const float* __restrict__ hidden, const float* __restrict__ out_w) {
    __shared__ float4 sxv[H / 4];
    __shared__ float4 shv[H / 4];
    const int tid = threadIdx.x;
    if (blockIdx.x >= 384) {
        pf_stream((const float4*)out_w + SEG3_OFF, SEG3_LEN, blockIdx.x - 384);
        return;
    }
    sxv[tid] = *(const float4*)(&g_x[tid * 4]);
    shv[tid] = *(const float4*)(hidden + tid * 4);
    __syncthreads();
    const int warp = tid >> 5, lane = tid & 31;
    const int row = blockIdx.x * 8 + warp;
    const float4* wi = (const float4*)(w_ih + (size_t)row * H);
    const float4* wh = (const float4*)(w_hh + (size_t)row * H);
    float4 a[8], b[8];
    #pragma unroll
    for (int k = 0; k < 8; k++) a[k] = wi[lane + 32 * k];
    #pragma unroll
    for (int k = 0; k < 8; k++) b[k] = wh[lane + 32 * k];
    float ai = 0.0f, ah = 0.0f;
    #pragma unroll
    for (int k = 0; k < 8; k++) {
        float4 x4 = sxv[lane + 32 * k];
        float4 h4 = shv[lane + 32 * k];
        ai += DOT4(a[k], x4);
        ah += DOT4(b[k], h4);
    }
    ai = warp_sum(ai);
    ah = warp_sum(ah);
    if (lane == 0) {
        g_gi[row] = ai + b_ih[row];
        g_gh[row] = ah + b_hh[row];
    }
}

// ---------------- 5) GRU gate combine -> h_new + prefetch role ----------------
// grid = 4 + NPF
__global__ void k_hnew(const float* __restrict__ hidden, float* __restrict__ out_h,
                       const float* __restrict__ out_w) {
    if (blockIdx.x >= 4) {
        pf_stream((const float4*)out_w + SEG4_OFF, SEG4_LEN, blockIdx.x - 4);
        return;
    }
    const int j = blockIdx.x * blockDim.x + threadIdx.x;
    float r = sigmoidf_(g_gi[j]         + g_gh[j]);
    float z = sigmoidf_(g_gi[H + j]     + g_gh[H + j]);
    float n = tanhf(g_gi[2 * H + j] + r * g_gh[2 * H + j]);
    float h = (1.0f - z) * n + z * hidden[j];
    g_h[j]  = h;
    out_h[j] = h;
}

// ---------------- 6) logits: warp-per-row over 206 MB (proven best shape) ----------------
// grid = ceil(V/8) = 6283
__global__ void k_logits(const float* __restrict__ out_w, const float* __restrict__ out_b) {
    __shared__ float4 shv[H / 4];
    const int tid = threadIdx.x;
    shv[tid] = *(const float4*)(&g_h[tid * 4]);
    __syncthreads();
    const int warp = tid >> 5, lane = tid & 31;
    const int row = blockIdx.x * 8 + warp;
    if (row >= V) return;
    const float4* wr = (const float4*)(out_w + (size_t)row * H);
    float4 w[8];
    #pragma unroll
    for (int k = 0; k < 8; k++) w[k] = wr[lane + 32 * k];
    float acc = 0.0f;
    #pragma unroll
    for (int k = 0; k < 8; k++) { float4 h4 = shv[lane + 32 * k]; acc += DOT4(w[k], h4); }
    acc = warp_sum(acc);
    if (lane == 0) g_logits[row] = acc + out_b[row];
}

// ---------------- 7) partial log-sum-exp: 64 blocks ----------------
#define LSE_CHUNK 786    // 64*786 = 50304 >= V
__global__ void k_lse1() {
    __shared__ float s[32];
    __shared__ float bm;
    const int b = blockIdx.x;
    const int lo = b * LSE_CHUNK;
    const int hi = min(lo + LSE_CHUNK, V);
    float m = -INFINITY;
    for (int v = lo + threadIdx.x; v < hi; v += blockDim.x) m = fmaxf(m, g_logits[v]);
    m = blk_max(m, s);
    if (threadIdx.x == 0) bm = m;
    __syncthreads();
    float m0 = bm;
    float sum = 0.0f;
    for (int v = lo + threadIdx.x; v < hi; v += blockDim.x) sum += expf(g_logits[v] - m0);
    sum = blk_sum(sum, s);
    if (threadIdx.x == 0) {
        g_pmax[b] = m0;
        g_psum[b] = sum;
    }
}

// ---------------- 8) final log-softmax write with FUSED partial combine ----------------
__global__ void k_out(float* __restrict__ out) {
    __shared__ float sm_, sls;
    const int tid = threadIdx.x;
    if (tid < 32) {
        float m = fmaxf(g_pmax[tid], g_pmax[tid + 32]);
        m = warp_max(m);
        m = __shfl_sync(0xffffffffu, m, 0);
        float s2 = g_psum[tid] * expf(g_pmax[tid] - m)
                 + g_psum[tid + 32] * expf(g_pmax[tid + 32] - m);
        s2 = warp_sum(s2);
        if (tid == 0) { sm_ = m; sls = logf(s2); }
    }
    __syncthreads();
    const int v = blockIdx.x * blockDim.x + tid;
    if (v < V) out[v] = g_logits[v] - sm_ - sls;
}

// ---------------- launch ----------------
extern "C" void kernel_launch(void* const* d_in, const int* in_sizes, int n_in,
                              void* d_out, int out_size) {
    const int*   tok       = (const int*)  d_in[0];
    const float* hidden    = (const float*)d_in[1];
    const float* enc       = (const float*)d_in[2];
    const float* embedding = (const float*)d_in[3];
    const float* attn_w    = (const float*)d_in[4];
    const float* attn_b    = (const float*)d_in[5];
    const float* comb_w    = (const float*)d_in[6];
    const float* comb_b    = (const float*)d_in[7];
    const float* w_ih      = (const float*)d_in[8];
    const float* w_hh      = (const float*)d_in[9];
    const float* b_ih      = (const float*)d_in[10];
    const float* b_hh      = (const float*)d_in[11];
    const float* out_w     = (const float*)d_in[12];
    const float* out_b     = (const float*)d_in[13];
    float* out = (float*)d_out;

    // output layout: [log_softmax (V)] [h_new (H)] [attn_weights (L)]
    k_attn     <<<64  + NPF, 256>>>(tok, hidden, embedding, attn_w, attn_b, out_w);
    k_attnapply<<<64  + NPF, 256>>>(enc, out + V + H, out_w);
    k_comb     <<<128 + NPF, 256>>>(tok, embedding, comb_w, comb_b, out_w);
    k_gru      <<<384 + NPF, 256>>>(w_ih, w_hh, b_ih, b_hh, hidden, out_w);
    k_hnew     <<<4   + NPF, 256>>>(hidden, out + V, out_w);
    k_logits   <<<(V + 7) / 8, 256>>>(out_w, out_b);
    k_lse1     <<<64, 256>>>();
    k_out      <<<(V + 255) / 256, 256>>>(out);
}

// round 17
// speedup vs baseline: 1.1245x; 1.1245x over previous
#include <cuda_runtime.h>
#include <math.h>

#define V 50257
#define H 1024
#define E 1024
#define L 512
#define HE 2048
#define G3 3072
#define NP 16            // L-partitions for attn-apply (32 rows each)

// ---------------- scratch (no allocations allowed) ----------------
__device__ float g_attn_logits[L];
__device__ float g_att_part[NP * H];
__device__ float g_x[E];
__device__ float g_gi[G3];
__device__ float g_gh[G3];
__device__ float g_h[H];
__device__ float g_logits[V];
__device__ float g_pmax[64];
__device__ float g_psum[64];

__device__ __forceinline__ float warp_sum(float v) {
    #pragma unroll
    for (int o = 16; o; o >>= 1) v += __shfl_down_sync(0xffffffffu, v, o);
    return v;
}
__device__ __forceinline__ float warp_max(float v) {
    #pragma unroll
    for (int o = 16; o; o >>= 1) v = fmaxf(v, __shfl_down_sync(0xffffffffu, v, o));
    return v;
}
__device__ __forceinline__ float blk_sum(float v, float* s) {
    int lane = threadIdx.x & 31, w = threadIdx.x >> 5;
    v = warp_sum(v);
    if (lane == 0) s[w] = v;
    __syncthreads();
    int nw = (blockDim.x + 31) >> 5;
    v = (threadIdx.x < nw) ? s[threadIdx.x] : 0.0f;
    if (w == 0) v = warp_sum(v);
    __syncthreads();
    return v;
}
__device__ __forceinline__ float blk_max(float v, float* s) {
    int lane = threadIdx.x & 31, w = threadIdx.x >> 5;
    v = warp_max(v);
    if (lane == 0) s[w] = v;
    __syncthreads();
    int nw = (blockDim.x + 31) >> 5;
    v = (threadIdx.x < nw) ? s[threadIdx.x] : -INFINITY;
    if (w == 0) v = warp_max(v);
    __syncthreads();
    return v;
}
__device__ __forceinline__ float sigmoidf_(float x) { return 1.0f / (1.0f + expf(-x)); }

#define DOT4(a, b) ((a).x * (b).x + (a).y * (b).y + (a).z * (b).z + (a).w * (b).w)

// ---------------- 1) attention logits: warp-per-row over [emb,h0] (2048) ----------------
// grid = L/8 = 64, block = 256. Two explicit 8-load batches.
__global__ void k_attn(const int* __restrict__ tok, const float* __restrict__ hidden,
                       const float* __restrict__ embedding,
                       const float* __restrict__ attn_w, const float* __restrict__ attn_b) {
    __shared__ float4 sx[HE / 4];
    const int tid = threadIdx.x;
    {
        const float* emb = embedding + (size_t)tok[0] * E;
        sx[tid]       = *(const float4*)(emb + tid * 4);
        sx[tid + 256] = *(const float4*)(hidden + tid * 4);
    }
    __syncthreads();
    const int warp = tid >> 5, lane = tid & 31;
    const int row = blockIdx.x * 8 + warp;
    const float4* wr = (const float4*)(attn_w + (size_t)row * HE);
    float acc = 0.0f;
    float4 w[8];
    #pragma unroll
    for (int k = 0; k < 8; k++) w[k] = wr[lane + 32 * k];
    #pragma unroll
    for (int k = 0; k < 8; k++) { float4 x4 = sx[lane + 32 * k]; acc += DOT4(w[k], x4); }
    #pragma unroll
    for (int k = 0; k < 8; k++) w[k] = wr[256 + lane + 32 * k];
    #pragma unroll
    for (int k = 0; k < 8; k++) { float4 x4 = sx[256 + lane + 32 * k]; acc += DOT4(w[k], x4); }
    acc = warp_sum(acc);
    if (lane == 0) g_attn_logits[row] = acc + attn_b[row];
}

// ---------------- 2) attn partials with FUSED softmax: grid (4, NP) = 64 blocks ----------------
__global__ void k_attnapply(const float* __restrict__ enc, float* __restrict__ out_aw) {
    __shared__ float s[32];
    __shared__ float sl[L];
    __shared__ float aw[32];
    __shared__ float bm, bs;
    const int tid = threadIdx.x;
    sl[tid]       = g_attn_logits[tid];
    sl[tid + 256] = g_attn_logits[tid + 256];
    __syncthreads();
    float m = fmaxf(sl[tid], sl[tid + 256]);
    m = blk_max(m, s);
    if (tid == 0) bm = m;
    __syncthreads();
    float e = expf(sl[tid] - bm) + expf(sl[tid + 256] - bm);
    float sum = blk_sum(e, s);
    if (tid == 0) bs = sum;
    __syncthreads();
    const int r0 = blockIdx.y * 32;
    if (tid < 32) {
        float wv = expf(sl[r0 + tid] - bm) / bs;
        aw[tid] = wv;
        if (blockIdx.x == 0) out_aw[r0 + tid] = wv;
    }
    __syncthreads();
    const int col = blockIdx.x * blockDim.x + tid;
    float acc = 0.0f;
    #pragma unroll 8
    for (int l = 0; l < 32; l++) acc += aw[l] * enc[(size_t)(r0 + l) * H + col];
    g_att_part[blockIdx.y * H + col] = acc;
}

// ---------------- 3) x = relu([emb, att] @ comb_w.T + b): warp-per-row ----------------
// grid = E/8 = 128, block = 256.
__global__ void k_comb(const int* __restrict__ tok, const float* __restrict__ embedding,
                       const float* __restrict__ comb_w, const float* __restrict__ comb_b) {
    __shared__ float4 sx[HE / 4];
    const int tid = threadIdx.x;
    {
        const float* emb = embedding + (size_t)tok[0] * E;
        sx[tid] = *(const float4*)(emb + tid * 4);
        float4 a = make_float4(0.f, 0.f, 0.f, 0.f);
        #pragma unroll
        for (int p = 0; p < NP; p++) {
            float4 t = *(const float4*)(&g_att_part[p * H + tid * 4]);
            a.x += t.x; a.y += t.y; a.z += t.z; a.w += t.w;
        }
        sx[tid + 256] = a;
    }
    __syncthreads();
    const int warp = tid >> 5, lane = tid & 31;
    const int row = blockIdx.x * 8 + warp;
    const float4* wr = (const float4*)(comb_w + (size_t)row * HE);
    float acc = 0.0f;
    float4 w[8];
    #pragma unroll
    for (int k = 0; k < 8; k++) w[k] = wr[lane + 32 * k];
    #pragma unroll
    for (int k = 0; k < 8; k++) { float4 x4 = sx[lane + 32 * k]; acc += DOT4(w[k], x4); }
    #pragma unroll
    for (int k = 0; k < 8; k++) w[k] = wr[256 + lane + 32 * k];
    #pragma unroll
    for (int k = 0; k < 8; k++) { float4 x4 = sx[256 + lane + 32 * k]; acc += DOT4(w[k], x4); }
    acc = warp_sum(acc);
    if (lane == 0) g_x[row] = fmaxf(acc + comb_b[row], 0.0f);
}

// ---------------- 4) GRU matvecs: warp-per-row, 16 loads in flight (proven 3.0 TB/s) -----
// grid = 3072/8 = 384, block = 256.
__global__ void k_gru(const float* __restrict__ w_ih, const float* __restrict__ w_hh,
                      const float* __restrict__ b_ih, const float* __restrict__ b_hh,
                      const float* __restrict__ hidden) {
    __shared__ float4 sxv[H / 4];
    __shared__ float4 shv[H / 4];
    const int tid = threadIdx.x;
    sxv[tid] = *(const float4*)(&g_x[tid * 4]);
    shv[tid] = *(const float4*)(hidden + tid * 4);
    __syncthreads();
    const int warp = tid >> 5, lane = tid & 31;
    const int row = blockIdx.x * 8 + warp;
    const float4* wi = (const float4*)(w_ih + (size_t)row * H);
    const float4* wh = (const float4*)(w_hh + (size_t)row * H);
    float4 a[8], b[8];
    #pragma unroll
    for (int k = 0; k < 8; k++) a[k] = wi[lane + 32 * k];
    #pragma unroll
    for (int k = 0; k < 8; k++) b[k] = wh[lane + 32 * k];
    float ai = 0.0f, ah = 0.0f;
    #pragma unroll
    for (int k = 0; k < 8; k++) {
        float4 x4 = sxv[lane + 32 * k];
        float4 h4 = shv[lane + 32 * k];
        ai += DOT4(a[k], x4);
        ah += DOT4(b[k], h4);
    }
    ai = warp_sum(ai);
    ah = warp_sum(ah);
    if (lane == 0) {
        g_gi[row] = ai + b_ih[row];
        g_gh[row] = ah + b_hh[row];
    }
}

// ---------------- 5) GRU gate combine -> h_new ----------------
__global__ void k_hnew(const float* __restrict__ hidden, float* __restrict__ out_h) {
    const int j = blockIdx.x * blockDim.x + threadIdx.x;
    float r = sigmoidf_(g_gi[j]         + g_gh[j]);
    float z = sigmoidf_(g_gi[H + j]     + g_gh[H + j]);
    float n = tanhf(g_gi[2 * H + j] + r * g_gh[2 * H + j]);
    float h = (1.0f - z) * n + z * hidden[j];
    g_h[j]  = h;
    out_h[j] = h;
}

// ---------------- 6) logits: warp-per-row, NO smem staging / NO syncthreads ----------------
// grid = ceil(V/8) = 6283, block = 256. Each iteration: w4 from DRAM, h4 from L2-hot g_h.
// Removes the per-block 250-cycle staging prologue that throttled every prior shape.
__global__ void k_logits(const float* __restrict__ out_w, const float* __restrict__ out_b) {
    const int tid = threadIdx.x, warp = tid >> 5, lane = tid & 31;
    const int row = blockIdx.x * 8 + warp;
    if (row >= V) return;
    const float4* wr = (const float4*)(out_w + (size_t)row * H);
    const float4* hv = (const float4*)g_h;
    float4 w[8];
    #pragma unroll
    for (int k = 0; k < 8; k++) w[k] = wr[lane + 32 * k];
    float acc = 0.0f;
    #pragma unroll
    for (int k = 0; k < 8; k++) {
        float4 h4 = __ldg(hv + lane + 32 * k);
        acc += DOT4(w[k], h4);
    }
    acc = warp_sum(acc);
    if (lane == 0) g_logits[row] = acc + out_b[row];
}

// ---------------- 7) partial log-sum-exp: 64 blocks ----------------
#define LSE_CHUNK 786    // 64*786 = 50304 >= V
__global__ void k_lse1() {
    __shared__ float s[32];
    __shared__ float bm;
    const int b = blockIdx.x;
    const int lo = b * LSE_CHUNK;
    const int hi = min(lo + LSE_CHUNK, V);
    float m = -INFINITY;
    for (int v = lo + threadIdx.x; v < hi; v += blockDim.x) m = fmaxf(m, g_logits[v]);
    m = blk_max(m, s);
    if (threadIdx.x == 0) bm = m;
    __syncthreads();
    float m0 = bm;
    float sum = 0.0f;
    for (int v = lo + threadIdx.x; v < hi; v += blockDim.x) sum += expf(g_logits[v] - m0);
    sum = blk_sum(sum, s);
    if (threadIdx.x == 0) {
        g_pmax[b] = m0;
        g_psum[b] = sum;
    }
}

// ---------------- 8) final log-softmax write with FUSED partial combine ----------------
__global__ void k_out(float* __restrict__ out) {
    __shared__ float sm_, sls;
    const int tid = threadIdx.x;
    if (tid < 32) {
        float m = fmaxf(g_pmax[tid], g_pmax[tid + 32]);
        m = warp_max(m);
        m = __shfl_sync(0xffffffffu, m, 0);
        float s2 = g_psum[tid] * expf(g_pmax[tid] - m)
                 + g_psum[tid + 32] * expf(g_pmax[tid + 32] - m);
        s2 = warp_sum(s2);
        if (tid == 0) { sm_ = m; sls = logf(s2); }
    }
    __syncthreads();
    const int v = blockIdx.x * blockDim.x + tid;
    if (v < V) out[v] = g_logits[v] - sm_ - sls;
}

// ---------------- launch ----------------
extern "C" void kernel_launch(void* const* d_in, const int* in_sizes, int n_in,
                              void* d_out, int out_size) {
    const int*   tok       = (const int*)  d_in[0];
    const float* hidden    = (const float*)d_in[1];
    const float* enc       = (const float*)d_in[2];
    const float* embedding = (const float*)d_in[3];
    const float* attn_w    = (const float*)d_in[4];
    const float* attn_b    = (const float*)d_in[5];
    const float* comb_w    = (const float*)d_in[6];
    const float* comb_b    = (const float*)d_in[7];
    const float* w_ih      = (const float*)d_in[8];
    const float* w_hh      = (const float*)d_in[9];
    const float* b_ih      = (const float*)d_in[10];
    const float* b_hh      = (const float*)d_in[11];
    const float* out_w     = (const float*)d_in[12];
    const float* out_b     = (const float*)d_in[13];
    float* out = (float*)d_out;

    // output layout: [log_softmax (V)] [h_new (H)] [attn_weights (L)]
    k_attn     <<<L / 8, 256>>>(tok, hidden, embedding, attn_w, attn_b);
    k_attnapply<<<dim3(4, NP), 256>>>(enc, out + V + H);
    k_comb     <<<E / 8, 256>>>(tok, embedding, comb_w, comb_b);
    k_gru      <<<G3 / 8, 256>>>(w_ih, w_hh, b_ih, b_hh, hidden);
    k_hnew     <<<H / 256, 256>>>(hidden, out + V);
    k_logits   <<<(V + 7) / 8, 256>>>(out_w, out_b);
    k_lse1     <<<64, 256>>>();
    k_out      <<<(V + 255) / 256, 256>>>(out);
}